// round 15
// baseline (speedup 1.0000x reference)
#include <cuda_runtime.h>
#include <math.h>

// Problem constants (fixed by the reference setup_inputs)
#define NN 100000          // nodes
#define NE 3200000         // edges
#define NC 16              // classes

#define LBLOCKS 1024
#define LTHREADS 256

// ---- scratch (device globals; no allocations allowed) ----
__device__ __align__(16) float g_sums[NN * NC];   // scatter sums
__device__ float  g_cnt[NN];                      // in-degree (as float)
__device__ __align__(16) float g_ls[NN * NC];     // log(avg + 1e-10)
__device__ __align__(16) float g_d[NN * NC];      // sharp + 1e-10
__device__ float  g_dlogd[NN];                    // sum_c d*log(d)
__device__ float  g_partials[LBLOCKS];            // per-block loss partials

// Vectorized fp32 reduction to global memory (PTX ISA 8.1+, sm_90+).
// One L2 reduction op for 4 floats instead of 4 scalar REDs.
__device__ __forceinline__ void red_add_v4(float* addr, float a, float b,
                                           float c, float d) {
    asm volatile("red.global.add.v4.f32 [%0], {%1, %2, %3, %4};"
                 :: "l"(__cvta_generic_to_global(addr)),
                    "f"(a), "f"(b), "f"(c), "f"(d)
                 : "memory");
}

// ---------------------------------------------------------------------------
// K0: zero the accumulators (graph-replay safe: re-zeroed every launch)
// ---------------------------------------------------------------------------
__global__ void k_init() {
    int i = blockIdx.x * blockDim.x + threadIdx.x;
    int stride = gridDim.x * blockDim.x;
    float4 z = make_float4(0.f, 0.f, 0.f, 0.f);
    float4* s4 = reinterpret_cast<float4*>(g_sums);
    for (int j = i; j < (NN * NC) / 4; j += stride) s4[j] = z;
    for (int j = i; j < NN; j += stride) g_cnt[j] = 0.f;
}

// ---------------------------------------------------------------------------
// K1: scatter-add  sums[dst] += aug_pred[src],  cnt[dst] += 1
// One thread per edge; 4 x red.v4 + 1 scalar red.
// ---------------------------------------------------------------------------
__global__ void k_scatter(const int* __restrict__ src,
                          const int* __restrict__ dst,
                          const float4* __restrict__ aug4) {
    int e = blockIdx.x * blockDim.x + threadIdx.x;
    if (e >= NE) return;
    int s = src[e];
    int t = dst[e];
    float4 a0 = aug4[s * 4 + 0];
    float4 a1 = aug4[s * 4 + 1];
    float4 a2 = aug4[s * 4 + 2];
    float4 a3 = aug4[s * 4 + 3];
    float* base = g_sums + t * NC;
    red_add_v4(base +  0, a0.x, a0.y, a0.z, a0.w);
    red_add_v4(base +  4, a1.x, a1.y, a1.z, a1.w);
    red_add_v4(base +  8, a2.x, a2.y, a2.z, a2.w);
    red_add_v4(base + 12, a3.x, a3.y, a3.z, a3.w);
    atomicAdd(&g_cnt[t], 1.0f);
}

// ---------------------------------------------------------------------------
// K2: per-node epilogue
//   avg = sums / max(cnt,1);  p = avg^2 (TEMP=0.5);  sharp = p / sum(p)
//   ls = log(avg + 1e-10);  d = sharp + 1e-10;  dlogd = sum_c d*log(d)
// ---------------------------------------------------------------------------
__global__ void k_node() {
    int i = blockIdx.x * blockDim.x + threadIdx.x;
    if (i >= NN) return;

    float inv = 1.0f / fmaxf(g_cnt[i], 1.0f);
    const float4* s4 = reinterpret_cast<const float4*>(g_sums) + i * 4;

    float avg[NC];
#pragma unroll
    for (int k = 0; k < 4; k++) {
        float4 v = s4[k];
        avg[4 * k + 0] = v.x * inv;
        avg[4 * k + 1] = v.y * inv;
        avg[4 * k + 2] = v.z * inv;
        avg[4 * k + 3] = v.w * inv;
    }

    float p[NC];
    float psum = 0.f;
#pragma unroll
    for (int c = 0; c < NC; c++) { p[c] = avg[c] * avg[c]; psum += p[c]; }
    float invp = 1.0f / psum;

    float dv[NC], lsv[NC];
    float dlogd = 0.f;
#pragma unroll
    for (int c = 0; c < NC; c++) {
        float d = p[c] * invp + 1e-10f;
        dv[c]  = d;
        dlogd += d * logf(d);
        lsv[c] = logf(avg[c] + 1e-10f);
    }

    float4* d4  = reinterpret_cast<float4*>(g_d)  + i * 4;
    float4* ls4 = reinterpret_cast<float4*>(g_ls) + i * 4;
#pragma unroll
    for (int k = 0; k < 4; k++) {
        d4[k]  = make_float4(dv[4*k], dv[4*k+1], dv[4*k+2], dv[4*k+3]);
        ls4[k] = make_float4(lsv[4*k], lsv[4*k+1], lsv[4*k+2], lsv[4*k+3]);
    }
    g_dlogd[i] = dlogd;
}

// ---------------------------------------------------------------------------
// K3: edge loss  loss_e = dlogd[dst] - dot(d[dst], ls[src])
// Pure gather; per-block float partials (no global atomic hotspot).
// ---------------------------------------------------------------------------
__global__ void k_loss(const int* __restrict__ src,
                       const int* __restrict__ dst) {
    int tid = blockIdx.x * blockDim.x + threadIdx.x;
    int stride = gridDim.x * blockDim.x;
    const float4* ls4 = reinterpret_cast<const float4*>(g_ls);
    const float4* d4  = reinterpret_cast<const float4*>(g_d);

    float local = 0.f;
    for (int e = tid; e < NE; e += stride) {
        int s = src[e];
        int t = dst[e];
        float4 l0 = ls4[s * 4 + 0], l1 = ls4[s * 4 + 1];
        float4 l2 = ls4[s * 4 + 2], l3 = ls4[s * 4 + 3];
        float4 d0 = d4[t * 4 + 0],  d1 = d4[t * 4 + 1];
        float4 d2 = d4[t * 4 + 2],  d3 = d4[t * 4 + 3];
        float dot = 0.f;
        dot = fmaf(d0.x, l0.x, dot); dot = fmaf(d0.y, l0.y, dot);
        dot = fmaf(d0.z, l0.z, dot); dot = fmaf(d0.w, l0.w, dot);
        dot = fmaf(d1.x, l1.x, dot); dot = fmaf(d1.y, l1.y, dot);
        dot = fmaf(d1.z, l1.z, dot); dot = fmaf(d1.w, l1.w, dot);
        dot = fmaf(d2.x, l2.x, dot); dot = fmaf(d2.y, l2.y, dot);
        dot = fmaf(d2.z, l2.z, dot); dot = fmaf(d2.w, l2.w, dot);
        dot = fmaf(d3.x, l3.x, dot); dot = fmaf(d3.y, l3.y, dot);
        dot = fmaf(d3.z, l3.z, dot); dot = fmaf(d3.w, l3.w, dot);
        local += g_dlogd[t] - dot;
    }

    // block reduce (float)
    __shared__ float sm[LTHREADS / 32];
#pragma unroll
    for (int o = 16; o > 0; o >>= 1)
        local += __shfl_xor_sync(0xffffffffu, local, o);
    if ((threadIdx.x & 31) == 0) sm[threadIdx.x >> 5] = local;
    __syncthreads();
    if (threadIdx.x < (LTHREADS / 32)) {
        float v = sm[threadIdx.x];
#pragma unroll
        for (int o = (LTHREADS / 64); o > 0; o >>= 1)
            v += __shfl_xor_sync(0x000000ffu, v, o);
        if (threadIdx.x == 0) g_partials[blockIdx.x] = v;
    }
}

// ---------------------------------------------------------------------------
// K4: final reduction of block partials (double), write scalar mean
// ---------------------------------------------------------------------------
__global__ void k_final(float* __restrict__ out) {
    __shared__ double sm[8];
    double v = 0.0;
    for (int j = threadIdx.x; j < LBLOCKS; j += blockDim.x)
        v += (double)g_partials[j];
#pragma unroll
    for (int o = 16; o > 0; o >>= 1)
        v += __shfl_xor_sync(0xffffffffu, v, o);
    if ((threadIdx.x & 31) == 0) sm[threadIdx.x >> 5] = v;
    __syncthreads();
    if (threadIdx.x == 0) {
        double t = 0.0;
#pragma unroll
        for (int k = 0; k < 8; k++) t += sm[k];
        out[0] = (float)(t / (double)NE);
    }
}

// ---------------------------------------------------------------------------
extern "C" void kernel_launch(void* const* d_in, const int* in_sizes, int n_in,
                              void* d_out, int out_size) {
    const int* edge = (const int*)d_in[0];          // [2, E] int32
    const int* src  = edge;                         // edge_index[0]
    const int* dst  = edge + NE;                    // edge_index[1]
    const float4* aug4 = (const float4*)d_in[1];    // [N, 16] fp32, 64B rows
    float* out = (float*)d_out;

    k_init<<<512, 256>>>();
    k_scatter<<<(NE + 255) / 256, 256>>>(src, dst, aug4);
    k_node<<<(NN + 255) / 256, 256>>>();
    k_loss<<<LBLOCKS, LTHREADS>>>(src, dst);
    k_final<<<1, 256>>>(out);
}

// round 16
// speedup vs baseline: 1.4153x; 1.4153x over previous
#include <cuda_runtime.h>
#include <math.h>

// Problem constants (fixed by the reference setup_inputs)
#define NN 100000          // nodes
#define NE 3200000         // edges  (= 12500 * 256 exactly)
#define NC 16              // classes
#define NCHUNK 98          // ceil(NN / 1024)
#define NODE_BLOCKS 12500  // NN / 8 warps-per-256-thread-block exactly
#define EDGE_BLOCKS 12500  // NE / 256 exactly

// ---- scratch (device globals; no allocations allowed) ----
__device__ unsigned g_cnt[NN];          // in-degree
__device__ unsigned g_off[NN];          // CSR row offsets (exclusive scan of cnt)
__device__ unsigned g_cursor[NN];       // reorder cursors
__device__ unsigned g_chunksum[NCHUNK];
__device__ unsigned g_chunkbase[NCHUNK];
__device__ int      g_csrc[NE];         // src ids sorted by dst (CSR adjacency)
__device__ __align__(16) float g_ls[NN * NC];  // log(avg + 1e-10)
__device__ __align__(16) float g_d[NN * NC];   // sharp + 1e-10
__device__ float    g_term[NN];         // deg * sum_c d*log(d)
__device__ float    g_partials[NODE_BLOCKS];

// ---------------------------------------------------------------------------
// K0: zero the degree counters (graph-replay safe)
// ---------------------------------------------------------------------------
__global__ void k_init() {
    int i = blockIdx.x * blockDim.x + threadIdx.x;
    if (i < NN) g_cnt[i] = 0u;
}

// ---------------------------------------------------------------------------
// K1: in-degree histogram (scalar u32 REDs, spread across 100K addresses)
// ---------------------------------------------------------------------------
__global__ void k_hist(const int* __restrict__ dst) {
    int e = blockIdx.x * blockDim.x + threadIdx.x;
    atomicAdd(&g_cnt[dst[e]], 1u);
}

// ---------------------------------------------------------------------------
// K2a/b/c: exclusive scan of g_cnt -> g_off  (chunked: 98 x 1024)
// ---------------------------------------------------------------------------
__global__ void k_scanA() {
    __shared__ unsigned wsum[32];
    int t = threadIdx.x;
    int i = blockIdx.x * 1024 + t;
    unsigned v = (i < NN) ? g_cnt[i] : 0u;
    unsigned inc = v;
#pragma unroll
    for (int o = 1; o < 32; o <<= 1) {
        unsigned n = __shfl_up_sync(0xffffffffu, inc, o);
        if ((t & 31) >= o) inc += n;
    }
    if ((t & 31) == 31) wsum[t >> 5] = inc;
    __syncthreads();
    if (t < 32) {
        unsigned w = wsum[t];
#pragma unroll
        for (int o = 1; o < 32; o <<= 1) {
            unsigned n = __shfl_up_sync(0xffffffffu, w, o);
            if (t >= o) w += n;
        }
        wsum[t] = w;  // inclusive scan of the 32 warp totals
    }
    __syncthreads();
    unsigned base = (t >= 32) ? wsum[(t >> 5) - 1] : 0u;
    if (i < NN) g_off[i] = base + inc - v;          // block-local exclusive
    if (t == 0) g_chunksum[blockIdx.x] = wsum[31];  // chunk total
}

__global__ void k_scanB() {   // 1 block, 128 threads: scan the 98 chunk totals
    __shared__ unsigned wsum[4];
    int t = threadIdx.x;
    unsigned v = (t < NCHUNK) ? g_chunksum[t] : 0u;
    unsigned inc = v;
#pragma unroll
    for (int o = 1; o < 32; o <<= 1) {
        unsigned n = __shfl_up_sync(0xffffffffu, inc, o);
        if ((t & 31) >= o) inc += n;
    }
    if ((t & 31) == 31) wsum[t >> 5] = inc;
    __syncthreads();
    if (t < 4) {
        unsigned w = wsum[t];
#pragma unroll
        for (int o = 1; o < 4; o <<= 1) {
            unsigned n = __shfl_up_sync(0x0000000fu, w, o);
            if (t >= o) w += n;
        }
        wsum[t] = w;
    }
    __syncthreads();
    unsigned base = (t >= 32) ? wsum[(t >> 5) - 1] : 0u;
    if (t < NCHUNK) g_chunkbase[t] = base + inc - v;
}

__global__ void k_scanC() {   // add chunk bases; also seed reorder cursors
    int i = blockIdx.x * 1024 + threadIdx.x;
    if (i < NN) {
        unsigned v = g_off[i] + g_chunkbase[blockIdx.x];
        g_off[i]    = v;
        g_cursor[i] = v;
    }
}

// ---------------------------------------------------------------------------
// K3: counting-sort reorder — src ids grouped by dst (CSR adjacency)
// ---------------------------------------------------------------------------
__global__ void k_reorder(const int* __restrict__ src,
                          const int* __restrict__ dst) {
    int e = blockIdx.x * blockDim.x + threadIdx.x;
    int s = src[e];
    int t = dst[e];
    unsigned p = atomicAdd(&g_cursor[t], 1u);
    g_csrc[p] = s;
}

// ---------------------------------------------------------------------------
// K4: warp-per-node — gather-sum aug rows (NO atomics), full epilogue.
//   4-lane groups each own one 16B quarter-row (sub); 8 edges per warp-iter.
//   avg = sum/deg; p = avg^2 (TEMP=0.5); d = p/sum(p)+1e-10; ls = log(avg+1e-10)
//   g_term = deg * sum_c d*log(d)   (folds the dlogd[dst] edge sum)
// ---------------------------------------------------------------------------
__global__ void __launch_bounds__(256) k_nodesum(const float4* __restrict__ aug4) {
    int node = (blockIdx.x * 256 + threadIdx.x) >> 5;
    int lane = threadIdx.x & 31;
    int grp = lane >> 2;
    int sub = lane & 3;
    unsigned start = g_off[node];
    unsigned deg   = g_cnt[node];   // >= 1 guaranteed by construction

    float4 acc = make_float4(0.f, 0.f, 0.f, 0.f);
    for (unsigned k = grp; k < deg; k += 8) {
        int s = g_csrc[start + k];                 // 4-lane broadcast
        float4 a = __ldg(&aug4[s * 4 + sub]);      // 64B coalesced per group
        acc.x += a.x; acc.y += a.y; acc.z += a.z; acc.w += a.w;
    }
    // reduce across the 8 groups (lanes sharing `sub`)
#pragma unroll
    for (int o = 4; o < 32; o <<= 1) {
        acc.x += __shfl_xor_sync(0xffffffffu, acc.x, o);
        acc.y += __shfl_xor_sync(0xffffffffu, acc.y, o);
        acc.z += __shfl_xor_sync(0xffffffffu, acc.z, o);
        acc.w += __shfl_xor_sync(0xffffffffu, acc.w, o);
    }

    float inv = 1.0f / (float)deg;
    float4 avg = make_float4(acc.x * inv, acc.y * inv, acc.z * inv, acc.w * inv);
    float4 p = make_float4(avg.x * avg.x, avg.y * avg.y,
                           avg.z * avg.z, avg.w * avg.w);
    float psum = p.x + p.y + p.z + p.w;
    psum += __shfl_xor_sync(0xffffffffu, psum, 1);
    psum += __shfl_xor_sync(0xffffffffu, psum, 2);
    float invp = 1.0f / psum;

    float4 d = make_float4(p.x * invp + 1e-10f, p.y * invp + 1e-10f,
                           p.z * invp + 1e-10f, p.w * invp + 1e-10f);
    float4 ls = make_float4(logf(avg.x + 1e-10f), logf(avg.y + 1e-10f),
                            logf(avg.z + 1e-10f), logf(avg.w + 1e-10f));
    float dl = d.x * logf(d.x) + d.y * logf(d.y)
             + d.z * logf(d.z) + d.w * logf(d.w);
    dl += __shfl_xor_sync(0xffffffffu, dl, 1);
    dl += __shfl_xor_sync(0xffffffffu, dl, 2);

    if (lane < 4) {
        reinterpret_cast<float4*>(g_d)[node * 4 + sub]  = d;
        reinterpret_cast<float4*>(g_ls)[node * 4 + sub] = ls;
        if (lane == 0) g_term[node] = (float)deg * dl;
    }
}

// ---------------------------------------------------------------------------
// K5: warp-per-node loss:  node_j = deg_j*dlogd_j - dot(d_j, sum_{in(j)} ls[src])
//   d row lives in registers (one load/node); only ls[src] is gathered.
// ---------------------------------------------------------------------------
__global__ void __launch_bounds__(256) k_loss() {
    int node = (blockIdx.x * 256 + threadIdx.x) >> 5;
    int lane = threadIdx.x & 31;
    int grp = lane >> 2;
    int sub = lane & 3;
    unsigned start = g_off[node];
    unsigned deg   = g_cnt[node];
    const float4* ls4 = reinterpret_cast<const float4*>(g_ls);

    float4 S = make_float4(0.f, 0.f, 0.f, 0.f);
    for (unsigned k = grp; k < deg; k += 8) {
        int s = g_csrc[start + k];
        float4 a = __ldg(&ls4[s * 4 + sub]);
        S.x += a.x; S.y += a.y; S.z += a.z; S.w += a.w;
    }
#pragma unroll
    for (int o = 4; o < 32; o <<= 1) {
        S.x += __shfl_xor_sync(0xffffffffu, S.x, o);
        S.y += __shfl_xor_sync(0xffffffffu, S.y, o);
        S.z += __shfl_xor_sync(0xffffffffu, S.z, o);
        S.w += __shfl_xor_sync(0xffffffffu, S.w, o);
    }

    float4 d = reinterpret_cast<const float4*>(g_d)[node * 4 + sub];
    float dot = fmaf(d.x, S.x, fmaf(d.y, S.y, fmaf(d.z, S.z, d.w * S.w)));
    dot += __shfl_xor_sync(0xffffffffu, dot, 1);
    dot += __shfl_xor_sync(0xffffffffu, dot, 2);

    float local = (lane == 0) ? (g_term[node] - dot) : 0.f;

    __shared__ float sm[8];
    if (lane == 0) sm[threadIdx.x >> 5] = local;
    __syncthreads();
    if (threadIdx.x < 8) {
        float v = sm[threadIdx.x];
        v += __shfl_xor_sync(0x000000ffu, v, 1);
        v += __shfl_xor_sync(0x000000ffu, v, 2);
        v += __shfl_xor_sync(0x000000ffu, v, 4);
        if (threadIdx.x == 0) g_partials[blockIdx.x] = v;
    }
}

// ---------------------------------------------------------------------------
// K6: final reduction of block partials (double), write scalar mean
// ---------------------------------------------------------------------------
__global__ void k_final(float* __restrict__ out) {
    __shared__ double sm[8];
    double v = 0.0;
    for (int j = threadIdx.x; j < NODE_BLOCKS; j += 256)
        v += (double)g_partials[j];
#pragma unroll
    for (int o = 16; o > 0; o >>= 1)
        v += __shfl_xor_sync(0xffffffffu, v, o);
    if ((threadIdx.x & 31) == 0) sm[threadIdx.x >> 5] = v;
    __syncthreads();
    if (threadIdx.x == 0) {
        double t = 0.0;
#pragma unroll
        for (int k = 0; k < 8; k++) t += sm[k];
        out[0] = (float)(t / (double)NE);
    }
}

// ---------------------------------------------------------------------------
extern "C" void kernel_launch(void* const* d_in, const int* in_sizes, int n_in,
                              void* d_out, int out_size) {
    const int* edge = (const int*)d_in[0];          // [2, E] int32
    const int* src  = edge;                         // edge_index[0]
    const int* dst  = edge + NE;                    // edge_index[1]
    const float4* aug4 = (const float4*)d_in[1];    // [N, 16] fp32, 64B rows
    float* out = (float*)d_out;

    k_init<<<NCHUNK, 1024>>>();
    k_hist<<<EDGE_BLOCKS, 256>>>(dst);
    k_scanA<<<NCHUNK, 1024>>>();
    k_scanB<<<1, 128>>>();
    k_scanC<<<NCHUNK, 1024>>>();
    k_reorder<<<EDGE_BLOCKS, 256>>>(src, dst);
    k_nodesum<<<NODE_BLOCKS, 256>>>(aug4);
    k_loss<<<NODE_BLOCKS, 256>>>();
    k_final<<<1, 256>>>(out);
}

// round 17
// speedup vs baseline: 1.4530x; 1.0266x over previous
#include <cuda_runtime.h>
#include <math.h>

// Problem constants (fixed by the reference setup_inputs)
#define NN 100000          // nodes
#define NE 3200000         // edges  (= 12500 * 256 exactly)
#define NC 16              // classes
#define NCHUNK 98          // ceil(NN / 1024)
#define NODE_BLOCKS 12500  // NN / 8 warps-per-256-thread-block exactly
#define EDGE_BLOCKS 12500  // NE / 256 exactly

// ---- scratch (device globals; no allocations allowed) ----
__device__ unsigned g_cnt[NN];          // in-degree
__device__ unsigned g_off[NN];          // CSR row offsets (exclusive scan of cnt)
__device__ unsigned g_cursor[NN];       // reorder cursors
__device__ unsigned g_chunksum[NCHUNK];
__device__ unsigned g_chunkbase[NCHUNK];
__device__ int      g_csrc[NE];         // src ids sorted by dst (CSR adjacency)
__device__ __align__(16) float g_ls[NN * NC];  // log(avg + 1e-10)
__device__ __align__(16) float g_d[NN * NC];   // sharp + 1e-10
__device__ float    g_term[NN];         // deg * sum_c d*log(d)
__device__ float    g_partials[NODE_BLOCKS];

// ---------------------------------------------------------------------------
// K0: zero the degree counters (graph-replay safe)
// ---------------------------------------------------------------------------
__global__ void k_init() {
    int i = blockIdx.x * blockDim.x + threadIdx.x;
    if (i < NN) g_cnt[i] = 0u;
}

// ---------------------------------------------------------------------------
// K1: in-degree histogram (scalar u32 REDs, spread across 100K addresses)
// ---------------------------------------------------------------------------
__global__ void k_hist(const int* __restrict__ dst) {
    int e = blockIdx.x * blockDim.x + threadIdx.x;
    atomicAdd(&g_cnt[dst[e]], 1u);
}

// ---------------------------------------------------------------------------
// K2a/b/c: exclusive scan of g_cnt -> g_off  (chunked: 98 x 1024)
// ---------------------------------------------------------------------------
__global__ void k_scanA() {
    __shared__ unsigned wsum[32];
    int t = threadIdx.x;
    int i = blockIdx.x * 1024 + t;
    unsigned v = (i < NN) ? g_cnt[i] : 0u;
    unsigned inc = v;
#pragma unroll
    for (int o = 1; o < 32; o <<= 1) {
        unsigned n = __shfl_up_sync(0xffffffffu, inc, o);
        if ((t & 31) >= o) inc += n;
    }
    if ((t & 31) == 31) wsum[t >> 5] = inc;
    __syncthreads();
    if (t < 32) {
        unsigned w = wsum[t];
#pragma unroll
        for (int o = 1; o < 32; o <<= 1) {
            unsigned n = __shfl_up_sync(0xffffffffu, w, o);
            if (t >= o) w += n;
        }
        wsum[t] = w;  // inclusive scan of the 32 warp totals
    }
    __syncthreads();
    unsigned base = (t >= 32) ? wsum[(t >> 5) - 1] : 0u;
    if (i < NN) g_off[i] = base + inc - v;          // block-local exclusive
    if (t == 0) g_chunksum[blockIdx.x] = wsum[31];  // chunk total
}

__global__ void k_scanB() {   // 1 block, 128 threads: scan the 98 chunk totals
    __shared__ unsigned wsum[4];
    int t = threadIdx.x;
    unsigned v = (t < NCHUNK) ? g_chunksum[t] : 0u;
    unsigned inc = v;
#pragma unroll
    for (int o = 1; o < 32; o <<= 1) {
        unsigned n = __shfl_up_sync(0xffffffffu, inc, o);
        if ((t & 31) >= o) inc += n;
    }
    if ((t & 31) == 31) wsum[t >> 5] = inc;
    __syncthreads();
    if (t < 4) {
        unsigned w = wsum[t];
#pragma unroll
        for (int o = 1; o < 4; o <<= 1) {
            unsigned n = __shfl_up_sync(0x0000000fu, w, o);
            if (t >= o) w += n;
        }
        wsum[t] = w;
    }
    __syncthreads();
    unsigned base = (t >= 32) ? wsum[(t >> 5) - 1] : 0u;
    if (t < NCHUNK) g_chunkbase[t] = base + inc - v;
}

__global__ void k_scanC() {   // add chunk bases; also seed reorder cursors
    int i = blockIdx.x * 1024 + threadIdx.x;
    if (i < NN) {
        unsigned v = g_off[i] + g_chunkbase[blockIdx.x];
        g_off[i]    = v;
        g_cursor[i] = v;
    }
}

// ---------------------------------------------------------------------------
// K3: counting-sort reorder — src ids grouped by dst (CSR adjacency)
// ---------------------------------------------------------------------------
__global__ void k_reorder(const int* __restrict__ src,
                          const int* __restrict__ dst) {
    int e = blockIdx.x * blockDim.x + threadIdx.x;
    int s = src[e];
    int t = dst[e];
    unsigned p = atomicAdd(&g_cursor[t], 1u);
    g_csrc[p] = s;
}

// ---------------------------------------------------------------------------
// K4: warp-per-node — gather-sum aug rows (NO atomics), full epilogue.
//   4-lane groups each own one 16B quarter-row (sub); 8 edges per warp-iter.
//   avg = sum/deg; p = avg^2 (TEMP=0.5); d = p/sum(p)+1e-10; ls = log(avg+1e-10)
//   g_term = deg * sum_c d*log(d)   (folds the dlogd[dst] edge sum)
// ---------------------------------------------------------------------------
__global__ void __launch_bounds__(256) k_nodesum(const float4* __restrict__ aug4) {
    int node = (blockIdx.x * 256 + threadIdx.x) >> 5;
    int lane = threadIdx.x & 31;
    int grp = lane >> 2;
    int sub = lane & 3;
    unsigned start = g_off[node];
    unsigned deg   = g_cnt[node];   // >= 1 guaranteed by construction

    float4 acc = make_float4(0.f, 0.f, 0.f, 0.f);
    for (unsigned k = grp; k < deg; k += 8) {
        int s = g_csrc[start + k];                 // 4-lane broadcast
        float4 a = __ldg(&aug4[s * 4 + sub]);      // 64B coalesced per group
        acc.x += a.x; acc.y += a.y; acc.z += a.z; acc.w += a.w;
    }
    // reduce across the 8 groups (lanes sharing `sub`)
#pragma unroll
    for (int o = 4; o < 32; o <<= 1) {
        acc.x += __shfl_xor_sync(0xffffffffu, acc.x, o);
        acc.y += __shfl_xor_sync(0xffffffffu, acc.y, o);
        acc.z += __shfl_xor_sync(0xffffffffu, acc.z, o);
        acc.w += __shfl_xor_sync(0xffffffffu, acc.w, o);
    }

    float inv = 1.0f / (float)deg;
    float4 avg = make_float4(acc.x * inv, acc.y * inv, acc.z * inv, acc.w * inv);
    float4 p = make_float4(avg.x * avg.x, avg.y * avg.y,
                           avg.z * avg.z, avg.w * avg.w);
    float psum = p.x + p.y + p.z + p.w;
    psum += __shfl_xor_sync(0xffffffffu, psum, 1);
    psum += __shfl_xor_sync(0xffffffffu, psum, 2);
    float invp = 1.0f / psum;

    float4 d = make_float4(p.x * invp + 1e-10f, p.y * invp + 1e-10f,
                           p.z * invp + 1e-10f, p.w * invp + 1e-10f);
    float4 ls = make_float4(logf(avg.x + 1e-10f), logf(avg.y + 1e-10f),
                            logf(avg.z + 1e-10f), logf(avg.w + 1e-10f));
    float dl = d.x * logf(d.x) + d.y * logf(d.y)
             + d.z * logf(d.z) + d.w * logf(d.w);
    dl += __shfl_xor_sync(0xffffffffu, dl, 1);
    dl += __shfl_xor_sync(0xffffffffu, dl, 2);

    if (lane < 4) {
        reinterpret_cast<float4*>(g_d)[node * 4 + sub]  = d;
        reinterpret_cast<float4*>(g_ls)[node * 4 + sub] = ls;
        if (lane == 0) g_term[node] = (float)deg * dl;
    }
}

// ---------------------------------------------------------------------------
// K5: warp-per-node loss:  node_j = deg_j*dlogd_j - dot(d_j, sum_{in(j)} ls[src])
//   d row lives in registers (one load/node); only ls[src] is gathered.
// ---------------------------------------------------------------------------
__global__ void __launch_bounds__(256) k_loss() {
    int node = (blockIdx.x * 256 + threadIdx.x) >> 5;
    int lane = threadIdx.x & 31;
    int grp = lane >> 2;
    int sub = lane & 3;
    unsigned start = g_off[node];
    unsigned deg   = g_cnt[node];
    const float4* ls4 = reinterpret_cast<const float4*>(g_ls);

    float4 S = make_float4(0.f, 0.f, 0.f, 0.f);
    for (unsigned k = grp; k < deg; k += 8) {
        int s = g_csrc[start + k];
        float4 a = __ldg(&ls4[s * 4 + sub]);
        S.x += a.x; S.y += a.y; S.z += a.z; S.w += a.w;
    }
#pragma unroll
    for (int o = 4; o < 32; o <<= 1) {
        S.x += __shfl_xor_sync(0xffffffffu, S.x, o);
        S.y += __shfl_xor_sync(0xffffffffu, S.y, o);
        S.z += __shfl_xor_sync(0xffffffffu, S.z, o);
        S.w += __shfl_xor_sync(0xffffffffu, S.w, o);
    }

    float4 d = reinterpret_cast<const float4*>(g_d)[node * 4 + sub];
    float dot = fmaf(d.x, S.x, fmaf(d.y, S.y, fmaf(d.z, S.z, d.w * S.w)));
    dot += __shfl_xor_sync(0xffffffffu, dot, 1);
    dot += __shfl_xor_sync(0xffffffffu, dot, 2);

    float local = (lane == 0) ? (g_term[node] - dot) : 0.f;

    __shared__ float sm[8];
    if (lane == 0) sm[threadIdx.x >> 5] = local;
    __syncthreads();
    if (threadIdx.x < 8) {
        float v = sm[threadIdx.x];
        v += __shfl_xor_sync(0x000000ffu, v, 1);
        v += __shfl_xor_sync(0x000000ffu, v, 2);
        v += __shfl_xor_sync(0x000000ffu, v, 4);
        if (threadIdx.x == 0) g_partials[blockIdx.x] = v;
    }
}

// ---------------------------------------------------------------------------
// K6: final reduction of block partials (double), write scalar mean
// ---------------------------------------------------------------------------
__global__ void k_final(float* __restrict__ out) {
    __shared__ double sm[8];
    double v = 0.0;
    for (int j = threadIdx.x; j < NODE_BLOCKS; j += 256)
        v += (double)g_partials[j];
#pragma unroll
    for (int o = 16; o > 0; o >>= 1)
        v += __shfl_xor_sync(0xffffffffu, v, o);
    if ((threadIdx.x & 31) == 0) sm[threadIdx.x >> 5] = v;
    __syncthreads();
    if (threadIdx.x == 0) {
        double t = 0.0;
#pragma unroll
        for (int k = 0; k < 8; k++) t += sm[k];
        out[0] = (float)(t / (double)NE);
    }
}

// ---------------------------------------------------------------------------
extern "C" void kernel_launch(void* const* d_in, const int* in_sizes, int n_in,
                              void* d_out, int out_size) {
    const int* edge = (const int*)d_in[0];          // [2, E] int32
    const int* src  = edge;                         // edge_index[0]
    const int* dst  = edge + NE;                    // edge_index[1]
    const float4* aug4 = (const float4*)d_in[1];    // [N, 16] fp32, 64B rows
    float* out = (float*)d_out;

    k_init<<<NCHUNK, 1024>>>();
    k_hist<<<EDGE_BLOCKS, 256>>>(dst);
    k_scanA<<<NCHUNK, 1024>>>();
    k_scanB<<<1, 128>>>();
    k_scanC<<<NCHUNK, 1024>>>();
    k_reorder<<<EDGE_BLOCKS, 256>>>(src, dst);
    k_nodesum<<<NODE_BLOCKS, 256>>>(aug4);
    k_loss<<<NODE_BLOCKS, 256>>>();
    k_final<<<1, 256>>>(out);
}